// round 1
// baseline (speedup 1.0000x reference)
#include <cuda_runtime.h>
#include <mma.h>
#include <math.h>

using namespace nvcuda;

// Problem dims
constexpr int Bb   = 512;   // batch
constexpr int Tt_  = 128;   // timesteps
constexpr int Dd   = 128;   // input dim (x); X_seq row has D+1=129 floats
constexpr int Hh   = 512;   // hidden
constexpr int MEMN = 64;    // attention memory

constexpr int N1 = 6 * Hh;        // 3072 (6 gates)
constexpr int K1 = Hh + Dd + 1;   // 641  ([h | x | dt])
constexpr int N2 = 5 * Hh;        // 2560 (5 gates from s)
constexpr int K2 = Hh;            // 512

// GEMM tile config: 128x128 CTA tile, 8 warps (4x2), warp tile 32x64, K-chunk 64
constexpr int LDA = 68;    // 64 + 4 pad (floats)
constexpr int LDB = 132;   // 128 + 4 pad (floats)
constexpr int SMEM_BYTES = (128 * LDA + 64 * LDB) * 4;  // 68608; Cs (128x128 f32) overlaps

// ---------------- device scratch (no allocations allowed) ----------------
__device__ float g_h   [Bb * Hh];            // h_t (fp32)
__device__ float g_c   [Bb * Hh];            // c_t
__device__ float g_s   [Bb * Hh];            // s_t
__device__ float g_G   [Bb * N2];            // pre_h[1..5]+pre_x[1..5] sums
__device__ float g_A   [Bb * N2];            // activated gates f,i,T,z,o
__device__ float g_hist[MEMN * Bb * Hh];     // last 64 h_t, layout [m][b][h]
__device__ float g_qbuf[Bb * 2 * Hh];        // [h_last | c_last]
__device__ float g_xlast[Bb * Dd];
__device__ float g_qW  [Bb * Hh];            // q @ Waq
__device__ float g_hsW [MEMN * Bb * Hh];     // hs @ Wah, rows r = m*512+b
__device__ float g_scores[Bb * MEMN];
__device__ float g_e   [Bb * Hh];
__device__ float g_hfin[Bb * Hh];

// ---------------- wmma helpers ----------------
using FragA = wmma::fragment<wmma::matrix_a, 16, 16, 8, wmma::precision::tf32, wmma::row_major>;
using FragB = wmma::fragment<wmma::matrix_b, 16, 16, 8, wmma::precision::tf32, wmma::row_major>;
using FragC = wmma::fragment<wmma::accumulator, 16, 16, 8, float>;

__device__ __forceinline__ void mma_chunk(FragC (&acc)[2][4], const float* As, const float* Bs,
                                          int wm, int wn) {
#pragma unroll
    for (int kk = 0; kk < 64; kk += 8) {
        FragA a0, a1;
        wmma::load_matrix_sync(a0, As + (wm * 32) * LDA + kk, LDA);
        wmma::load_matrix_sync(a1, As + (wm * 32 + 16) * LDA + kk, LDA);
#pragma unroll
        for (int j = 0; j < 4; j++) {
            FragB bf;
            wmma::load_matrix_sync(bf, Bs + kk * LDB + wn * 64 + j * 16, LDB);
            wmma::mma_sync(acc[0][j], a0, bf, acc[0][j]);
            wmma::mma_sync(acc[1][j], a1, bf, acc[1][j]);
        }
    }
}

__device__ __forceinline__ void store_acc(FragC (&acc)[2][4], float* Cs, int wm, int wn) {
#pragma unroll
    for (int i = 0; i < 2; i++)
#pragma unroll
        for (int j = 0; j < 4; j++)
            wmma::store_matrix_sync(Cs + (wm * 32 + i * 16) * 128 + wn * 64 + j * 16,
                                    acc[i][j], 128, wmma::mem_row_major);
}

__device__ __forceinline__ float sigmoidf_(float x) { return 1.f / (1.f + expf(-x)); }

// ---------------- GEMM1: pre = [h|x|dt] @ [Wh;Wx;Wst], epilogue -> s, G ----------------
__global__ void k_gemm1(const float* __restrict__ X,
                        const float* __restrict__ Wh, const float* __restrict__ Wx,
                        const float* __restrict__ Wst,
                        const float* __restrict__ bh_lin, const float* __restrict__ bx_lin,
                        const float* __restrict__ bg, const float* __restrict__ bst, int t) {
    extern __shared__ float sm[];
    float* As = sm;
    float* Bs = sm + 128 * LDA;
    float* Cs = sm;
    const int tid = threadIdx.x, wid = tid >> 5, wm = wid >> 1, wn = wid & 1;
    const int row0 = blockIdx.y * 128, col0 = blockIdx.x * 128;

    FragC acc[2][4];
#pragma unroll
    for (int i = 0; i < 2; i++)
#pragma unroll
        for (int j = 0; j < 4; j++) wmma::fill_fragment(acc[i][j], 0.f);

    for (int kc = 0; kc < K1; kc += 64) {
        for (int e = tid; e < 8192; e += 256) {
            int r = e >> 6, k = e & 63, kg = kc + k;
            float v = 0.f;
            if (kg < K1) {
                int b = row0 + r;
                v = (kg < Hh) ? g_h[b * Hh + kg]
                              : X[(b * Tt_ + t) * (Dd + 1) + (kg - Hh)];
            }
            As[r * LDA + k] = wmma::__float_to_tf32(v);
        }
        for (int e = tid; e < 8192; e += 256) {
            int k = e >> 7, cc = e & 127, kg = kc + k;
            int j = col0 + cc, g = j >> 9, hh = j & 511;
            float v = 0.f;
            if (kg < K1) {
                if (kg < Hh)            v = Wh[(g * Hh + kg) * Hh + hh];
                else if (kg < Hh + Dd)  v = Wx[(g * Dd + (kg - Hh)) * Hh + hh];
                else                    v = (g == 0) ? Wst[hh] : 0.f;
            }
            Bs[k * LDB + cc] = wmma::__float_to_tf32(v);
        }
        __syncthreads();
        mma_chunk(acc, As, Bs, wm, wn);
        __syncthreads();
    }
    store_acc(acc, Cs, wm, wn);
    __syncthreads();
    for (int e = tid; e < 16384; e += 256) {
        int r = e >> 7, cc = e & 127;
        int b = row0 + r, j = col0 + cc, g = j >> 9, hh = j & 511;
        float val = Cs[e] + bh_lin[j] + bx_lin[j] + bg[j];
        if (g == 0) {
            val += bst[hh];
            g_s[b * Hh + hh] = tanhf(val);
        } else {
            g_G[b * N2 + (j - Hh)] = val;
        }
    }
}

// ---------------- GEMM2: pre_s = s @ Ws, epilogue -> activated gates ----------------
__global__ void k_gemm2(const float* __restrict__ Ws, const float* __restrict__ bs_lin) {
    extern __shared__ float sm[];
    float* As = sm;
    float* Bs = sm + 128 * LDA;
    float* Cs = sm;
    const int tid = threadIdx.x, wid = tid >> 5, wm = wid >> 1, wn = wid & 1;
    const int row0 = blockIdx.y * 128, col0 = blockIdx.x * 128;

    FragC acc[2][4];
#pragma unroll
    for (int i = 0; i < 2; i++)
#pragma unroll
        for (int j = 0; j < 4; j++) wmma::fill_fragment(acc[i][j], 0.f);

    for (int kc = 0; kc < K2; kc += 64) {
        for (int e = tid; e < 8192; e += 256) {
            int r = e >> 6, k = e & 63, kg = kc + k;
            As[r * LDA + k] = wmma::__float_to_tf32(g_s[(row0 + r) * Hh + kg]);
        }
        for (int e = tid; e < 8192; e += 256) {
            int k = e >> 7, cc = e & 127, kg = kc + k;
            int j = col0 + cc, g = j >> 9, hh = j & 511;
            Bs[k * LDB + cc] = wmma::__float_to_tf32(Ws[(g * Hh + kg) * Hh + hh]);
        }
        __syncthreads();
        mma_chunk(acc, As, Bs, wm, wn);
        __syncthreads();
    }
    store_acc(acc, Cs, wm, wn);
    __syncthreads();
    for (int e = tid; e < 16384; e += 256) {
        int r = e >> 7, cc = e & 127;
        int b = row0 + r, j = col0 + cc, g = j >> 9;
        float val = Cs[e] + g_G[b * N2 + j] + bs_lin[j];
        // gate order: f(0),i(1),T(2): sigmoid; z(3): tanh; o(4): sigmoid
        g_A[b * N2 + j] = (g == 3) ? tanhf(val) : sigmoidf_(val);
    }
}

// ---------------- state update: c, h, history ----------------
__global__ void k_state(int t) {
    int idx = blockIdx.x * 256 + threadIdx.x;  // b*512 + h
    if (idx >= Bb * Hh) return;
    int b = idx >> 9, hh = idx & 511;
    int base = b * N2 + hh;
    float f  = g_A[base];
    float ii = g_A[base + Hh];
    float Tg = g_A[base + 2 * Hh];
    float z  = g_A[base + 3 * Hh];
    float o  = g_A[base + 4 * Hh];
    float cn = f * g_c[idx] + ii * z + Tg * g_s[idx];
    g_c[idx] = cn;
    float hv = o * tanhf(cn);
    g_h[idx] = hv;
    if (t >= Tt_ - MEMN) g_hist[(t - (Tt_ - MEMN)) * (Bb * Hh) + idx] = hv;
}

__global__ void k_init() {
    int idx = blockIdx.x * 256 + threadIdx.x;
    if (idx < Bb * Hh) { g_h[idx] = 0.f; g_c[idx] = 0.f; }
}

// ---------------- generic plain GEMM: C = A@B (+C if beta) ----------------
__global__ void k_gemm_plain(const float* __restrict__ A, int lda,
                             const float* __restrict__ Bp, int ldb,
                             float* __restrict__ C, int ldc, int K, int beta) {
    extern __shared__ float sm[];
    float* As = sm;
    float* Bs = sm + 128 * LDA;
    float* Cs = sm;
    const int tid = threadIdx.x, wid = tid >> 5, wm = wid >> 1, wn = wid & 1;
    const int row0 = blockIdx.y * 128, col0 = blockIdx.x * 128;

    FragC acc[2][4];
#pragma unroll
    for (int i = 0; i < 2; i++)
#pragma unroll
        for (int j = 0; j < 4; j++) wmma::fill_fragment(acc[i][j], 0.f);

    for (int kc = 0; kc < K; kc += 64) {
        for (int e = tid; e < 8192; e += 256) {
            int r = e >> 6, k = e & 63, kg = kc + k;
            float v = (kg < K) ? A[(row0 + r) * lda + kg] : 0.f;
            As[r * LDA + k] = wmma::__float_to_tf32(v);
        }
        for (int e = tid; e < 8192; e += 256) {
            int k = e >> 7, cc = e & 127, kg = kc + k;
            float v = (kg < K) ? Bp[kg * ldb + col0 + cc] : 0.f;
            Bs[k * LDB + cc] = wmma::__float_to_tf32(v);
        }
        __syncthreads();
        mma_chunk(acc, As, Bs, wm, wn);
        __syncthreads();
    }
    store_acc(acc, Cs, wm, wn);
    __syncthreads();
    for (int e = tid; e < 16384; e += 256) {
        int r = e >> 7, cc = e & 127;
        int idx = (row0 + r) * ldc + col0 + cc;
        C[idx] = Cs[e] + (beta ? C[idx] : 0.f);
    }
}

// ---------------- tail kernels ----------------
__global__ void k_prep(const float* __restrict__ X) {
    int idx = blockIdx.x * 256 + threadIdx.x;
    if (idx < Bb * 2 * Hh) {
        int b = idx >> 10, k = idx & 1023;
        g_qbuf[idx] = (k < Hh) ? g_h[b * Hh + k] : g_c[b * Hh + (k - Hh)];
    }
    if (idx < Bb * Dd) {
        int b = idx >> 7, d = idx & 127;
        g_xlast[idx] = X[(b * Tt_ + (Tt_ - 1)) * (Dd + 1) + d];
    }
}

__global__ void k_scores(const float* __restrict__ baq, const float* __restrict__ bah,
                         const float* __restrict__ vt) {
    int wid = threadIdx.x >> 5, lane = threadIdx.x & 31;
    int r = blockIdx.x * 8 + wid;   // r = m*512 + b
    int b = r & 511;
    float acc = 0.f;
    for (int hh = lane; hh < Hh; hh += 32) {
        float x = g_hsW[r * Hh + hh] + g_qW[b * Hh + hh] + baq[hh] + bah[hh];
        acc += tanhf(x) * vt[hh];
    }
#pragma unroll
    for (int o = 16; o; o >>= 1) acc += __shfl_down_sync(0xffffffffu, acc, o);
    if (lane == 0) g_scores[b * MEMN + (r >> 9)] = acc;
}

__global__ void k_softmax_e() {
    int b = blockIdx.x, tid = threadIdx.x;
    __shared__ float al[MEMN];
    __shared__ float ssum;
    if (tid < MEMN) al[tid] = expf(g_scores[b * MEMN + tid]);
    __syncthreads();
    if (tid == 0) {
        float s = 0.f;
        for (int m = 0; m < MEMN; m++) s += al[m];
        ssum = s;
    }
    __syncthreads();
    float inv = 1.f / ssum;
    for (int hh = tid; hh < Hh; hh += 256) {
        float acc = 0.f;
        for (int m = 0; m < MEMN; m++)
            acc += al[m] * g_hist[m * (Bb * Hh) + b * Hh + hh];
        g_e[b * Hh + hh] = acc * inv;
    }
}

__global__ void k_final(const float* __restrict__ b_Wh, const float* __restrict__ b_We,
                        const float* __restrict__ b_Wg, const float* __restrict__ bh_p,
                        const float* __restrict__ Wc, const float* __restrict__ bc,
                        float* __restrict__ out) {
    int b = blockIdx.x, tid = threadIdx.x;
    __shared__ float red[256];
    float acc = 0.f;
    for (int hh = tid; hh < Hh; hh += 256) {
        float hf = tanhf(g_hfin[b * Hh + hh] + b_Wh[hh] + b_We[hh] + b_Wg[hh] + bh_p[hh]);
        acc += hf * Wc[hh];
    }
    red[tid] = acc;
    __syncthreads();
    for (int s = 128; s; s >>= 1) {
        if (tid < s) red[tid] += red[tid + s];
        __syncthreads();
    }
    if (tid == 0) out[b] = 1.f / (1.f + expf(-(red[0] + bc[0])));
}

// ---------------- launch ----------------
extern "C" void kernel_launch(void* const* d_in, const int* in_sizes, int n_in,
                              void* d_out, int out_size) {
    const float* X      = (const float*)d_in[0];
    const float* Wh     = (const float*)d_in[1];
    const float* bh_lin = (const float*)d_in[2];
    const float* Wx     = (const float*)d_in[3];
    const float* bx_lin = (const float*)d_in[4];
    const float* Wst    = (const float*)d_in[5];
    const float* bst    = (const float*)d_in[6];
    const float* Ws     = (const float*)d_in[7];
    const float* bs_lin = (const float*)d_in[8];
    const float* bg     = (const float*)d_in[9];
    const float* Waq    = (const float*)d_in[10];
    const float* baq    = (const float*)d_in[11];
    const float* Wah    = (const float*)d_in[12];
    const float* bah    = (const float*)d_in[13];
    const float* vt     = (const float*)d_in[14];
    const float* W_h    = (const float*)d_in[15];
    const float* b_Wh   = (const float*)d_in[16];
    const float* We     = (const float*)d_in[17];
    const float* b_We   = (const float*)d_in[18];
    const float* Wg     = (const float*)d_in[19];
    const float* b_Wg   = (const float*)d_in[20];
    const float* bh_p   = (const float*)d_in[21];
    const float* Wc     = (const float*)d_in[22];
    const float* bc     = (const float*)d_in[23];
    float* out = (float*)d_out;

    cudaFuncSetAttribute(k_gemm1,      cudaFuncAttributeMaxDynamicSharedMemorySize, SMEM_BYTES);
    cudaFuncSetAttribute(k_gemm2,      cudaFuncAttributeMaxDynamicSharedMemorySize, SMEM_BYTES);
    cudaFuncSetAttribute(k_gemm_plain, cudaFuncAttributeMaxDynamicSharedMemorySize, SMEM_BYTES);

    float *p_qbuf, *p_hist, *p_qW, *p_hsW, *p_h, *p_e, *p_xlast, *p_hfin;
    cudaGetSymbolAddress((void**)&p_qbuf,  g_qbuf);
    cudaGetSymbolAddress((void**)&p_hist,  g_hist);
    cudaGetSymbolAddress((void**)&p_qW,    g_qW);
    cudaGetSymbolAddress((void**)&p_hsW,   g_hsW);
    cudaGetSymbolAddress((void**)&p_h,     g_h);
    cudaGetSymbolAddress((void**)&p_e,     g_e);
    cudaGetSymbolAddress((void**)&p_xlast, g_xlast);
    cudaGetSymbolAddress((void**)&p_hfin,  g_hfin);

    k_init<<<1024, 256>>>();

    for (int t = 0; t < Tt_; t++) {
        k_gemm1<<<dim3(N1 / 128, Bb / 128), 256, SMEM_BYTES>>>(X, Wh, Wx, Wst,
                                                               bh_lin, bx_lin, bg, bst, t);
        k_gemm2<<<dim3(N2 / 128, Bb / 128), 256, SMEM_BYTES>>>(Ws, bs_lin);
        k_state<<<(Bb * Hh) / 256, 256>>>(t);
    }

    // attention + readout
    k_prep<<<(Bb * 2 * Hh + 255) / 256, 256>>>(X);
    k_gemm_plain<<<dim3(4, 4),   256, SMEM_BYTES>>>(p_qbuf, 2 * Hh, Waq, Hh, p_qW, Hh, 2 * Hh, 0);
    k_gemm_plain<<<dim3(4, 256), 256, SMEM_BYTES>>>(p_hist, Hh, Wah, Hh, p_hsW, Hh, Hh, 0);
    k_scores<<<(MEMN * Bb) / 8, 256>>>(baq, bah, vt);
    k_softmax_e<<<Bb, 256>>>();
    k_gemm_plain<<<dim3(4, 4), 256, SMEM_BYTES>>>(p_h,     Hh, W_h, Hh, p_hfin, Hh, Hh, 0);
    k_gemm_plain<<<dim3(4, 4), 256, SMEM_BYTES>>>(p_e,     Hh, We,  Hh, p_hfin, Hh, Hh, 1);
    k_gemm_plain<<<dim3(4, 4), 256, SMEM_BYTES>>>(p_xlast, Dd, Wg,  Hh, p_hfin, Hh, Dd, 1);
    k_final<<<Bb, 256>>>(b_Wh, b_We, b_Wg, bh_p, Wc, bc, out);
}

// round 2
// speedup vs baseline: 5.1060x; 5.1060x over previous
#include <cuda_runtime.h>
#include <cuda_bf16.h>
#include <mma.h>
#include <math.h>
#include <stdint.h>

using namespace nvcuda;
using bf16 = __nv_bfloat16;

// ---------------- problem dims ----------------
constexpr int Bb = 512, Tt = 128, Dd = 128, Hh = 512, MEMN = 64;
constexpr int N1 = 3072;            // 6 gates
constexpr int K1P = 672;            // [h 512 | x 128 | dt 1 | pad 31]
constexpr int N2 = 2560;            // 5 gates from s
constexpr int K2 = 512;

// ---------------- persistent kernel config ----------------
constexpr int NCTA = 128, NTHR = 256;
constexpr int W1_COLS = 48,  W1_LD = 680;
constexpr int W2_COLS = 80,  W2_LD = 520;
constexpr int SA_LD   = 40;                       // staged A row stride (elts)
constexpr int AST_ELTS = 256 * SA_LD;             // per buffer
constexpr size_t SM_AST = (size_t)2 * AST_ELTS * sizeof(bf16);   // 40960
constexpr size_t SM_W1  = (size_t)W1_COLS * W1_LD * sizeof(bf16); // 65280
constexpr size_t SM_W2  = (size_t)W2_COLS * W2_LD * sizeof(bf16); // 83200
constexpr size_t SM_TOTAL = SM_AST + SM_W1 + SM_W2;               // 189440

// ---------------- device scratch ----------------
__device__ bf16  g_AB[Bb * K1P];            // A matrix for phase1: [h | x_t | dt | pad]
__device__ bf16  g_sB[Bb * Hh];             // s_t (bf16)
__device__ float g_G [Bb * N2];             // pre_h[1..5]+pre_x[1..5]+biases
__device__ float g_c [Bb * Hh];
__device__ float g_h [Bb * Hh];
__device__ bf16  g_histB[MEMN * Bb * Hh];   // last 64 h, [m][b][h]
__device__ float g_bias1[N1];
__device__ unsigned g_cnt;
// tail
__device__ float g_qbuf[Bb * 2 * Hh];
__device__ float g_xlast[Bb * Dd];
__device__ float g_qW  [Bb * Hh];
__device__ bf16  g_WahB[Hh * Hh];           // Wah transposed, n-major [n][k]
__device__ float g_hsW [MEMN * Bb * Hh];
__device__ float g_scores[Bb * MEMN];
__device__ float g_e   [Bb * Hh];
__device__ float g_hfin[Bb * Hh];

// ---------------- small helpers ----------------
__device__ __forceinline__ float sigmoidf_(float x) { return 1.f / (1.f + expf(-x)); }

__device__ __forceinline__ void cp16(bf16* dst_smem, const bf16* src) {
    uint32_t d = (uint32_t)__cvta_generic_to_shared(dst_smem);
    asm volatile("cp.async.cg.shared.global [%0], [%1], 16;" :: "r"(d), "l"(src));
}
__device__ __forceinline__ void cp_commit() { asm volatile("cp.async.commit_group;"); }
template <int N>
__device__ __forceinline__ void cp_wait() { asm volatile("cp.async.wait_group %0;" :: "n"(N)); }

__device__ __forceinline__ uint32_t ld2bf(const bf16* p) {
    return *reinterpret_cast<const uint32_t*>(p);
}

__device__ __forceinline__ void mma16816(float* c, uint32_t a0, uint32_t a1, uint32_t a2,
                                         uint32_t a3, uint32_t b0, uint32_t b1) {
    asm volatile(
        "mma.sync.aligned.m16n8k16.row.col.f32.bf16.bf16.f32 "
        "{%0,%1,%2,%3}, {%4,%5,%6,%7}, {%8,%9}, {%0,%1,%2,%3};"
        : "+f"(c[0]), "+f"(c[1]), "+f"(c[2]), "+f"(c[3])
        : "r"(a0), "r"(a1), "r"(a2), "r"(a3), "r"(b0), "r"(b1));
}

// monotonic grid barrier (g_cnt reset by init kernel each launch)
__device__ __forceinline__ void gridbar(unsigned target) {
    __syncthreads();
    if (threadIdx.x == 0) {
        __threadfence();
        atomicAdd(&g_cnt, 1u);
        unsigned v;
        do {
            asm volatile("ld.acquire.gpu.u32 %0, [%1];" : "=r"(v) : "l"(&g_cnt) : "memory");
        } while (v < target);
    }
    __syncthreads();
}

// ---------------- init ----------------
__global__ void k_init2(const float* __restrict__ X, const float* __restrict__ bh_lin,
                        const float* __restrict__ bx_lin, const float* __restrict__ bg,
                        const float* __restrict__ bst) {
    int idx = blockIdx.x * 256 + threadIdx.x;
    if (idx == 0) g_cnt = 0;
    if (idx < N1) {
        float v = bh_lin[idx] + bx_lin[idx] + bg[idx];
        if (idx < 512) v += bst[idx];
        g_bias1[idx] = v;
    }
    if (idx < Bb * Hh) g_c[idx] = 0.f;
    if (idx < Bb * K1P) {
        int b = idx / K1P, cc = idx - b * K1P;
        float v = 0.f;
        if (cc >= 512 && cc < 641) v = X[((size_t)b * Tt + 0) * (Dd + 1) + (cc - 512)];
        g_AB[idx] = __float2bfloat16(v);
    }
}

// ---------------- persistent recurrent kernel ----------------
__global__ void __launch_bounds__(NTHR, 1)
k_recur(const float* __restrict__ X,
        const float* __restrict__ Wh, const float* __restrict__ Wx,
        const float* __restrict__ Wst,
        const float* __restrict__ Ws, const float* __restrict__ bs_lin) {
    extern __shared__ bf16 sm[];
    bf16* ast = sm;
    bf16* w1s = sm + 2 * AST_ELTS;
    bf16* w2s = w1s + W1_COLS * W1_LD;

    const int tid = threadIdx.x, cta = blockIdx.x;
    const int w = tid >> 5, lane = tid & 31;
    const int lq = lane >> 2, lr = lane & 3;

    // phase1 mapping: 64 col-tiles (48) x 2 m-tiles (256)
    const int ci = cta >> 1, mi1 = cta & 1;
    const int col0 = ci * W1_COLS, m01 = mi1 * 256;
    // phase2 mapping: 32 hh-tiles (16) x 4 m-tiles (128)
    const int hi = cta >> 2, mi2 = cta & 3;
    const int hh0 = hi * 16, m02 = mi2 * 128;

    // ---- load weight slices (once per launch) ----
    for (int idx = tid; idx < W1_COLS * K1P; idx += NTHR) {
        int n = idx / K1P, k = idx - n * K1P;
        int col = col0 + n, g = col >> 9, hh = col & 511;
        float v = 0.f;
        if (k < 512)      v = Wh[((size_t)(g * 512 + k)) * 512 + hh];
        else if (k < 640) v = Wx[((size_t)(g * 128 + (k - 512))) * 512 + hh];
        else if (k == 640) v = (g == 0) ? Wst[hh] : 0.f;
        w1s[n * W1_LD + k] = __float2bfloat16(v);
    }
    // W2 slice: storage row nl = (p*5+q)*8 + c  <->  global col = q*512 + hh0 + p*8 + c
    for (int idx = tid; idx < W2_COLS * K2; idx += NTHR) {
        int nl = idx / K2, k = idx - nl * K2;
        int blk = nl >> 3, c = nl & 7, p = blk / 5, q = blk - p * 5;
        int hh = hh0 + p * 8 + c;
        w2s[nl * W2_LD + k] = __float2bfloat16(Ws[((size_t)(q * 512 + k)) * 512 + hh]);
    }
    __syncthreads();

    const int wm1 = w >> 1, wn1 = w & 1;   // phase1 warp: 64 rows x 24 cols
    const int wm2 = w >> 1, wn2 = w & 1;   // phase2 warp: 32 rows x 40 cols (5 gates x 8 hh)

    unsigned bar = 0;

    for (int t = 0; t < Tt; t++) {
        // ============ phase 1: pre = [h|x|dt] @ W1 -> s, G ============
        {
            float acc[4][3][4];
#pragma unroll
            for (int i = 0; i < 4; i++)
#pragma unroll
                for (int j = 0; j < 3; j++)
#pragma unroll
                    for (int r = 0; r < 4; r++) acc[i][j][r] = 0.f;

            // stage chunk 0 (256 rows x 32 k)
            {
                const bf16* src = g_AB + (size_t)(m01 + tid) * K1P;
                bf16* dst = ast + tid * SA_LD;
                cp16(dst, src); cp16(dst + 8, src + 8);
                cp16(dst + 16, src + 16); cp16(dst + 24, src + 24);
                cp_commit();
            }
            for (int ch = 0; ch < 21; ch++) {
                if (ch < 20) {
                    const bf16* src = g_AB + (size_t)(m01 + tid) * K1P + (ch + 1) * 32;
                    bf16* dst = ast + ((ch + 1) & 1) * AST_ELTS + tid * SA_LD;
                    cp16(dst, src); cp16(dst + 8, src + 8);
                    cp16(dst + 16, src + 16); cp16(dst + 24, src + 24);
                    cp_commit();
                    cp_wait<1>();
                } else {
                    cp_wait<0>();
                }
                __syncthreads();
                const bf16* ab = ast + (ch & 1) * AST_ELTS;
                const int kc = ch * 32;
#pragma unroll
                for (int half = 0; half < 2; half++) {
                    const int kk = half * 16;
                    uint32_t areg[4][4];
#pragma unroll
                    for (int im = 0; im < 4; im++) {
                        const bf16* ap = ab + (wm1 * 64 + im * 16 + lq) * SA_LD + kk + lr * 2;
                        areg[im][0] = ld2bf(ap);
                        areg[im][1] = ld2bf(ap + 8 * SA_LD);
                        areg[im][2] = ld2bf(ap + 8);
                        areg[im][3] = ld2bf(ap + 8 * SA_LD + 8);
                    }
#pragma unroll
                    for (int jn = 0; jn < 3; jn++) {
                        const bf16* bp = w1s + (wn1 * 24 + jn * 8 + lq) * W1_LD + kc + kk + lr * 2;
                        uint32_t b0 = ld2bf(bp), b1 = ld2bf(bp + 8);
#pragma unroll
                        for (int im = 0; im < 4; im++)
                            mma16816(acc[im][jn], areg[im][0], areg[im][1],
                                     areg[im][2], areg[im][3], b0, b1);
                    }
                }
                __syncthreads();
            }
            // epilogue: s (gate 0, tanh, bf16) and G (gates 1..5, fp32)
#pragma unroll
            for (int im = 0; im < 4; im++) {
                int rbase = m01 + wm1 * 64 + im * 16 + lq;
#pragma unroll
                for (int jn = 0; jn < 3; jn++) {
                    int cbase = col0 + wn1 * 24 + jn * 8 + lr * 2;
#pragma unroll
                    for (int hf = 0; hf < 2; hf++) {
                        int row = rbase + hf * 8;
#pragma unroll
                        for (int e = 0; e < 2; e++) {
                            int col = cbase + e;
                            float val = acc[im][jn][hf * 2 + e] + g_bias1[col];
                            if (col < 512)
                                g_sB[row * 512 + col] = __float2bfloat16(tanhf(val));
                            else
                                g_G[(size_t)row * N2 + (col - 512)] = val;
                        }
                    }
                }
            }
        }
        bar += NCTA; gridbar(bar);

        // ============ phase 2: pre_s = s @ W2, fused gate+state update ============
        {
            float acc[2][5][4];
#pragma unroll
            for (int i = 0; i < 2; i++)
#pragma unroll
                for (int j = 0; j < 5; j++)
#pragma unroll
                    for (int r = 0; r < 4; r++) acc[i][j][r] = 0.f;

            // stage chunk 0 (128 rows x 32 k): thread -> (row=tid/2, part=tid&1)
            {
                int row = tid >> 1, part = tid & 1;
                const bf16* src = g_sB + (size_t)(m02 + row) * 512 + part * 16;
                bf16* dst = ast + row * SA_LD + part * 16;
                cp16(dst, src); cp16(dst + 8, src + 8);
                cp_commit();
            }
            for (int ch = 0; ch < 16; ch++) {
                if (ch < 15) {
                    int row = tid >> 1, part = tid & 1;
                    const bf16* src = g_sB + (size_t)(m02 + row) * 512 + (ch + 1) * 32 + part * 16;
                    bf16* dst = ast + ((ch + 1) & 1) * AST_ELTS + row * SA_LD + part * 16;
                    cp16(dst, src); cp16(dst + 8, src + 8);
                    cp_commit();
                    cp_wait<1>();
                } else {
                    cp_wait<0>();
                }
                __syncthreads();
                const bf16* ab = ast + (ch & 1) * AST_ELTS;
                const int kc = ch * 32;
#pragma unroll
                for (int half = 0; half < 2; half++) {
                    const int kk = half * 16;
                    uint32_t areg[2][4];
#pragma unroll
                    for (int im = 0; im < 2; im++) {
                        const bf16* ap = ab + (wm2 * 32 + im * 16 + lq) * SA_LD + kk + lr * 2;
                        areg[im][0] = ld2bf(ap);
                        areg[im][1] = ld2bf(ap + 8 * SA_LD);
                        areg[im][2] = ld2bf(ap + 8);
                        areg[im][3] = ld2bf(ap + 8 * SA_LD + 8);
                    }
#pragma unroll
                    for (int q = 0; q < 5; q++) {
                        const bf16* bp = w2s + ((wn2 * 5 + q) * 8 + lq) * W2_LD + kc + kk + lr * 2;
                        uint32_t b0 = ld2bf(bp), b1 = ld2bf(bp + 8);
#pragma unroll
                        for (int im = 0; im < 2; im++)
                            mma16816(acc[im][q], areg[im][0], areg[im][1],
                                     areg[im][2], areg[im][3], b0, b1);
                    }
                }
                __syncthreads();
            }
            // epilogue: all 5 gates of (b,hh) are thread-local -> fused LSTM update
#pragma unroll
            for (int im = 0; im < 2; im++) {
#pragma unroll
                for (int hf = 0; hf < 2; hf++) {
                    int b = m02 + wm2 * 32 + im * 16 + lq + hf * 8;
#pragma unroll
                    for (int e = 0; e < 2; e++) {
                        int hh = hh0 + wn2 * 8 + lr * 2 + e;
                        float v[5];
#pragma unroll
                        for (int q = 0; q < 5; q++)
                            v[q] = acc[im][q][hf * 2 + e]
                                 + g_G[(size_t)b * N2 + q * 512 + hh]
                                 + bs_lin[q * 512 + hh];
                        float f  = sigmoidf_(v[0]);
                        float i_ = sigmoidf_(v[1]);
                        float Tg = sigmoidf_(v[2]);
                        float z  = tanhf(v[3]);
                        float o  = sigmoidf_(v[4]);
                        float s  = __bfloat162float(g_sB[b * 512 + hh]);
                        float cn = f * g_c[b * 512 + hh] + i_ * z + Tg * s;
                        g_c[b * 512 + hh] = cn;
                        float hv = o * tanhf(cn);
                        g_h[b * 512 + hh] = hv;
                        g_AB[(size_t)b * K1P + hh] = __float2bfloat16(hv);
                        if (t >= Tt - MEMN)
                            g_histB[(size_t)(t - (Tt - MEMN)) * (Bb * Hh) + b * 512 + hh] =
                                __float2bfloat16(hv);
                    }
                }
            }
            // stage x_{t+1} (+dt) into A matrix (done by hh-tile-0 CTAs)
            if (hi == 0 && t < Tt - 1) {
                for (int idx = tid; idx < 128 * 129; idx += NTHR) {
                    int r = idx / 129, d = idx - r * 129;
                    int b = m02 + r;
                    g_AB[(size_t)b * K1P + 512 + d] =
                        __float2bfloat16(X[((size_t)b * Tt + (t + 1)) * (Dd + 1) + d]);
                }
            }
        }
        bar += NCTA; gridbar(bar);
    }
}

// ---------------- tail: hsW = hist(bf16) @ WahB(bf16), bf16 mma, double-buffered ----------------
__global__ void __launch_bounds__(256) k_hsw() {
    __shared__ bf16 as[2][128 * SA_LD];
    __shared__ bf16 bs[2][128 * SA_LD];
    const int tid = threadIdx.x, w = tid >> 5, lane = tid & 31;
    const int lq = lane >> 2, lr = lane & 3;
    const int row0 = blockIdx.y * 128, col0 = blockIdx.x * 128;
    const int wm = w >> 1, wn = w & 1;   // warp: 32 rows x 64 cols

    float acc[2][8][4];
#pragma unroll
    for (int i = 0; i < 2; i++)
#pragma unroll
        for (int j = 0; j < 8; j++)
#pragma unroll
            for (int r = 0; r < 4; r++) acc[i][j][r] = 0.f;

    {
        int r = tid >> 1, part = tid & 1;
        const bf16* sa = g_histB + (size_t)(row0 + r) * 512 + part * 16;
        const bf16* sb = g_WahB + (size_t)(col0 + r) * 512 + part * 16;
        bf16* da = &as[0][r * SA_LD + part * 16];
        bf16* db = &bs[0][r * SA_LD + part * 16];
        cp16(da, sa); cp16(da + 8, sa + 8);
        cp16(db, sb); cp16(db + 8, sb + 8);
        cp_commit();
    }
    for (int ch = 0; ch < 16; ch++) {
        if (ch < 15) {
            int r = tid >> 1, part = tid & 1;
            const bf16* sa = g_histB + (size_t)(row0 + r) * 512 + (ch + 1) * 32 + part * 16;
            const bf16* sb = g_WahB + (size_t)(col0 + r) * 512 + (ch + 1) * 32 + part * 16;
            int buf = (ch + 1) & 1;
            bf16* da = &as[buf][r * SA_LD + part * 16];
            bf16* db = &bs[buf][r * SA_LD + part * 16];
            cp16(da, sa); cp16(da + 8, sa + 8);
            cp16(db, sb); cp16(db + 8, sb + 8);
            cp_commit();
            cp_wait<1>();
        } else {
            cp_wait<0>();
        }
        __syncthreads();
        const bf16* ab = as[ch & 1];
        const bf16* bb = bs[ch & 1];
#pragma unroll
        for (int half = 0; half < 2; half++) {
            const int kk = half * 16;
            uint32_t areg[2][4];
#pragma unroll
            for (int im = 0; im < 2; im++) {
                const bf16* ap = ab + (wm * 32 + im * 16 + lq) * SA_LD + kk + lr * 2;
                areg[im][0] = ld2bf(ap);
                areg[im][1] = ld2bf(ap + 8 * SA_LD);
                areg[im][2] = ld2bf(ap + 8);
                areg[im][3] = ld2bf(ap + 8 * SA_LD + 8);
            }
#pragma unroll
            for (int jn = 0; jn < 8; jn++) {
                const bf16* bp = bb + (wn * 64 + jn * 8 + lq) * SA_LD + kk + lr * 2;
                uint32_t b0 = ld2bf(bp), b1 = ld2bf(bp + 8);
#pragma unroll
                for (int im = 0; im < 2; im++)
                    mma16816(acc[im][jn], areg[im][0], areg[im][1],
                             areg[im][2], areg[im][3], b0, b1);
            }
        }
        __syncthreads();
    }
#pragma unroll
    for (int im = 0; im < 2; im++)
#pragma unroll
        for (int jn = 0; jn < 8; jn++)
#pragma unroll
            for (int hf = 0; hf < 2; hf++)
#pragma unroll
                for (int e = 0; e < 2; e++) {
                    int row = row0 + wm * 32 + im * 16 + lq + hf * 8;
                    int col = col0 + wn * 64 + jn * 8 + lr * 2 + e;
                    g_hsW[(size_t)row * 512 + col] = acc[im][jn][hf * 2 + e];
                }
}

__global__ void k_prepWah(const float* __restrict__ Wah) {
    int idx = blockIdx.x * 256 + threadIdx.x;
    if (idx < Hh * Hh) {
        int k = idx >> 9, n = idx & 511;
        g_WahB[n * 512 + k] = __float2bfloat16(Wah[k * 512 + n]);
    }
}

// ---------------- tf32 wmma plain GEMM (small tail GEMMs) ----------------
constexpr int LDA = 68, LDB = 132;
constexpr int SMEM_BYTES = (128 * LDA + 64 * LDB) * 4;

using FragA = wmma::fragment<wmma::matrix_a, 16, 16, 8, wmma::precision::tf32, wmma::row_major>;
using FragB = wmma::fragment<wmma::matrix_b, 16, 16, 8, wmma::precision::tf32, wmma::row_major>;
using FragC = wmma::fragment<wmma::accumulator, 16, 16, 8, float>;

__device__ __forceinline__ void mma_chunk(FragC (&acc)[2][4], const float* As, const float* Bs,
                                          int wm, int wn) {
#pragma unroll
    for (int kk = 0; kk < 64; kk += 8) {
        FragA a0, a1;
        wmma::load_matrix_sync(a0, As + (wm * 32) * LDA + kk, LDA);
        wmma::load_matrix_sync(a1, As + (wm * 32 + 16) * LDA + kk, LDA);
#pragma unroll
        for (int j = 0; j < 4; j++) {
            FragB bf;
            wmma::load_matrix_sync(bf, Bs + kk * LDB + wn * 64 + j * 16, LDB);
            wmma::mma_sync(acc[0][j], a0, bf, acc[0][j]);
            wmma::mma_sync(acc[1][j], a1, bf, acc[1][j]);
        }
    }
}

__global__ void k_gemm_plain(const float* __restrict__ A, int lda,
                             const float* __restrict__ Bp, int ldb,
                             float* __restrict__ C, int ldc, int K, int beta) {
    extern __shared__ float smf[];
    float* As = smf;
    float* Bs = smf + 128 * LDA;
    float* Cs = smf;
    const int tid = threadIdx.x, wid = tid >> 5, wm = wid >> 1, wn = wid & 1;
    const int row0 = blockIdx.y * 128, col0 = blockIdx.x * 128;

    FragC acc[2][4];
#pragma unroll
    for (int i = 0; i < 2; i++)
#pragma unroll
        for (int j = 0; j < 4; j++) wmma::fill_fragment(acc[i][j], 0.f);

    for (int kc = 0; kc < K; kc += 64) {
        for (int e = tid; e < 8192; e += 256) {
            int r = e >> 6, k = e & 63, kg = kc + k;
            float v = (kg < K) ? A[(size_t)(row0 + r) * lda + kg] : 0.f;
            As[r * LDA + k] = wmma::__float_to_tf32(v);
        }
        for (int e = tid; e < 8192; e += 256) {
            int k = e >> 7, cc = e & 127, kg = kc + k;
            float v = (kg < K) ? Bp[(size_t)kg * ldb + col0 + cc] : 0.f;
            Bs[k * LDB + cc] = wmma::__float_to_tf32(v);
        }
        __syncthreads();
        mma_chunk(acc, As, Bs, wm, wn);
        __syncthreads();
    }
#pragma unroll
    for (int i = 0; i < 2; i++)
#pragma unroll
        for (int j = 0; j < 4; j++)
            wmma::store_matrix_sync(Cs + (wm * 32 + i * 16) * 128 + wn * 64 + j * 16,
                                    acc[i][j], 128, wmma::mem_row_major);
    __syncthreads();
    for (int e = tid; e < 16384; e += 256) {
        int r = e >> 7, cc = e & 127;
        size_t idx = (size_t)(row0 + r) * ldc + col0 + cc;
        C[idx] = Cs[e] + (beta ? C[idx] : 0.f);
    }
}

// ---------------- tail elementwise kernels ----------------
__global__ void k_prep(const float* __restrict__ X) {
    int idx = blockIdx.x * 256 + threadIdx.x;
    if (idx < Bb * 2 * Hh) {
        int b = idx >> 10, k = idx & 1023;
        g_qbuf[idx] = (k < Hh) ? g_h[b * Hh + k] : g_c[b * Hh + (k - Hh)];
    }
    if (idx < Bb * Dd) {
        int b = idx >> 7, d = idx & 127;
        g_xlast[idx] = X[((size_t)b * Tt + (Tt - 1)) * (Dd + 1) + d];
    }
}

__global__ void k_scores(const float* __restrict__ baq, const float* __restrict__ bah,
                         const float* __restrict__ vt) {
    int wid = threadIdx.x >> 5, lane = threadIdx.x & 31;
    int r = blockIdx.x * 8 + wid;   // r = m*512 + b
    int b = r & 511;
    float acc = 0.f;
    for (int hh = lane; hh < Hh; hh += 32) {
        float x = g_hsW[(size_t)r * Hh + hh] + g_qW[b * Hh + hh] + baq[hh] + bah[hh];
        acc += tanhf(x) * vt[hh];
    }
#pragma unroll
    for (int o = 16; o; o >>= 1) acc += __shfl_down_sync(0xffffffffu, acc, o);
    if (lane == 0) g_scores[b * MEMN + (r >> 9)] = acc;
}

__global__ void k_softmax_e() {
    int b = blockIdx.x, tid = threadIdx.x;
    __shared__ float al[MEMN];
    __shared__ float ssum;
    if (tid < MEMN) al[tid] = expf(g_scores[b * MEMN + tid]);
    __syncthreads();
    if (tid == 0) {
        float s = 0.f;
        for (int m = 0; m < MEMN; m++) s += al[m];
        ssum = s;
    }
    __syncthreads();
    float inv = 1.f / ssum;
    for (int hh = tid; hh < Hh; hh += 256) {
        float acc = 0.f;
        for (int m = 0; m < MEMN; m++)
            acc += al[m] * __bfloat162float(g_histB[(size_t)m * (Bb * Hh) + b * Hh + hh]);
        g_e[b * Hh + hh] = acc * inv;
    }
}

__global__ void k_final(const float* __restrict__ b_Wh, const float* __restrict__ b_We,
                        const float* __restrict__ b_Wg, const float* __restrict__ bh_p,
                        const float* __restrict__ Wc, const float* __restrict__ bc,
                        float* __restrict__ out) {
    int b = blockIdx.x, tid = threadIdx.x;
    __shared__ float red[256];
    float acc = 0.f;
    for (int hh = tid; hh < Hh; hh += 256) {
        float hf = tanhf(g_hfin[b * Hh + hh] + b_Wh[hh] + b_We[hh] + b_Wg[hh] + bh_p[hh]);
        acc += hf * Wc[hh];
    }
    red[tid] = acc;
    __syncthreads();
    for (int s = 128; s; s >>= 1) {
        if (tid < s) red[tid] += red[tid + s];
        __syncthreads();
    }
    if (tid == 0) out[b] = 1.f / (1.f + expf(-(red[0] + bc[0])));
}

// ---------------- launch ----------------
extern "C" void kernel_launch(void* const* d_in, const int* in_sizes, int n_in,
                              void* d_out, int out_size) {
    const float* X      = (const float*)d_in[0];
    const float* Wh     = (const float*)d_in[1];
    const float* bh_lin = (const float*)d_in[2];
    const float* Wx     = (const float*)d_in[3];
    const float* bx_lin = (const float*)d_in[4];
    const float* Wst    = (const float*)d_in[5];
    const float* bst    = (const float*)d_in[6];
    const float* Ws     = (const float*)d_in[7];
    const float* bs_lin = (const float*)d_in[8];
    const float* bg     = (const float*)d_in[9];
    const float* Waq    = (const float*)d_in[10];
    const float* baq    = (const float*)d_in[11];
    const float* Wah    = (const float*)d_in[12];
    const float* bah    = (const float*)d_in[13];
    const float* vt     = (const float*)d_in[14];
    const float* W_h    = (const float*)d_in[15];
    const float* b_Wh   = (const float*)d_in[16];
    const float* We     = (const float*)d_in[17];
    const float* b_We   = (const float*)d_in[18];
    const float* Wg     = (const float*)d_in[19];
    const float* b_Wg   = (const float*)d_in[20];
    const float* bh_p   = (const float*)d_in[21];
    const float* Wc     = (const float*)d_in[22];
    const float* bc     = (const float*)d_in[23];
    float* out = (float*)d_out;

    cudaFuncSetAttribute(k_recur, cudaFuncAttributeMaxDynamicSharedMemorySize, (int)SM_TOTAL);
    cudaFuncSetAttribute(k_gemm_plain, cudaFuncAttributeMaxDynamicSharedMemorySize, SMEM_BYTES);

    float *p_qbuf, *p_qW, *p_h, *p_e, *p_xlast, *p_hfin;
    cudaGetSymbolAddress((void**)&p_qbuf,  g_qbuf);
    cudaGetSymbolAddress((void**)&p_qW,    g_qW);
    cudaGetSymbolAddress((void**)&p_h,     g_h);
    cudaGetSymbolAddress((void**)&p_e,     g_e);
    cudaGetSymbolAddress((void**)&p_xlast, g_xlast);
    cudaGetSymbolAddress((void**)&p_hfin,  g_hfin);

    k_init2<<<(Bb * K1P + 255) / 256, 256>>>(X, bh_lin, bx_lin, bg, bst);
    k_recur<<<NCTA, NTHR, SM_TOTAL>>>(X, Wh, Wx, Wst, Ws, bs_lin);

    // attention + readout
    k_prepWah<<<(Hh * Hh + 255) / 256, 256>>>(Wah);
    k_prep<<<(Bb * 2 * Hh + 255) / 256, 256>>>(X);
    k_gemm_plain<<<dim3(4, 4), 256, SMEM_BYTES>>>(p_qbuf, 2 * Hh, Waq, Hh, p_qW, Hh, 2 * Hh, 0);
    k_hsw<<<dim3(4, 256), 256>>>();
    k_scores<<<(MEMN * Bb) / 8, 256>>>(baq, bah, vt);
    k_softmax_e<<<Bb, 256>>>();
    k_gemm_plain<<<dim3(4, 4), 256, SMEM_BYTES>>>(p_h,     Hh, W_h, Hh, p_hfin, Hh, Hh, 0);
    k_gemm_plain<<<dim3(4, 4), 256, SMEM_BYTES>>>(p_e,     Hh, We,  Hh, p_hfin, Hh, Hh, 1);
    k_gemm_plain<<<dim3(4, 4), 256, SMEM_BYTES>>>(p_xlast, Dd, Wg,  Hh, p_hfin, Hh, Dd, 1);
    k_final<<<Bb, 256>>>(b_Wh, b_We, b_Wg, bh_p, Wc, bc, out);
}